// round 11
// baseline (speedup 1.0000x reference)
#include <cuda_runtime.h>
#include <cstdint>
#include <math.h>

// ---------------- device scratch (no allocation allowed) ----------------
__device__ uint32_t g_h1p[128*32*32*4];     // after conv1+bn1, binarized, packed
__device__ uint32_t g_h2p[128*16*16*4];
__device__ uint32_t g_h3p[128*16*16*8];
__device__ uint32_t g_h4p[128*8*8*8];
__device__ uint32_t g_h5p[128*8*8*16];
__device__ float    g_h6 [128*4*4*512];     // fp output after conv6/pool/bn6
__device__ uint32_t g_w2p[9*4*128];
__device__ uint32_t g_w3p[9*4*256];
__device__ uint32_t g_w4p[9*8*256];
__device__ uint32_t g_w5p[9*8*512];
__device__ uint32_t g_w6p[9*16*512];

// ---------------- weight bit-packing (device helper) ----------------
// w: HWIO [3,3,CI,CO] floats -> wp[(tap*IW + word)*CO + co], bit b = (w[tap, word*32+b, co] > 0)
__device__ __forceinline__ void pack_dev(const float* __restrict__ w, uint32_t* __restrict__ wp,
                                         int CI, int CO, int idx) {
    int IW = CI / 32;
    int total = 9 * IW * CO;
    if (idx >= total) return;
    int co   = idx % CO;
    int word = (idx / CO) % IW;
    int tap  = idx / (CO * IW);
    uint32_t bits = 0;
    #pragma unroll 8
    for (int b = 0; b < 32; b++) {
        float v = w[(tap * CI + word * 32 + b) * CO + co];   // coalesced across co
        bits |= (v > 0.f ? 1u : 0u) << b;
    }
    wp[(tap * IW + word) * CO + co] = bits;
}

// ---------------- conv1 (device helper): fp conv 3x3x3->128 + b1 + relu + bn1 + pack ----------
// Numerics bitwise-match the reference: zero-seeded sequential FMA chain over (ky,kx,ci);
// bias added after; relu; bn as separate __fmul_rn then __fadd_rn.
__device__ __forceinline__ void conv1_dev(const float* __restrict__ x, const float* __restrict__ w1,
                                          const float* __restrict__ b1, const float* __restrict__ s1,
                                          const float* __restrict__ t1, int bid, int tid) {
    // bid in [0, 2048): n = bid>>4 (128), yb = bid&15 (16); block handles rows 2yb, 2yb+1
    __shared__ float sx[4][34][3];
    int n = bid >> 4, yb = bid & 15;
    int half = tid >> 7, c = tid & 127;
    int y = 2 * yb + half;

    for (int i = tid; i < 4 * 34 * 3; i += 256) {
        int ci = i % 3;
        int xx = (i / 3) % 34;
        int r  = i / (3 * 34);
        int yy = 2 * yb - 1 + r;
        int xs = xx - 1;
        float v = 0.f;
        if (yy >= 0 && yy < 32 && xs >= 0 && xs < 32)
            v = x[((n * 32 + yy) * 32 + xs) * 3 + ci];
        sx[r][xx][ci] = v;
    }
    __syncthreads();

    float wr[27];
    #pragma unroll
    for (int k = 0; k < 27; k++) wr[k] = w1[k * 128 + c];
    float bb = b1[c], sc = s1[c], tc = t1[c];
    int lane = c & 31, wrp = c >> 5;

    for (int xo = 0; xo < 32; xo++) {
        float acc = 0.f;
        #pragma unroll
        for (int ky = 0; ky < 3; ky++)
            #pragma unroll
            for (int kx = 0; kx < 3; kx++)
                #pragma unroll
                for (int ci = 0; ci < 3; ci++)
                    acc = fmaf(sx[half + ky][xo + kx][ci], wr[(ky * 3 + kx) * 3 + ci], acc);
        float z = __fadd_rn(acc, bb);
        float r = fmaxf(z, 0.f);
        float v = __fadd_rn(__fmul_rn(r, sc), tc);
        unsigned m = __ballot_sync(0xffffffffu, v > 0.f);
        if (lane == 0) g_h1p[((n * 32 + y) * 32 + xo) * 4 + wrp] = m;
    }
}

// ---------------- fused prep: all 5 weight packs + conv1 (mutually independent) -------------
// block layout (256 threads each):
//   [0,18)    pack w2   [18,54)  pack w3   [54,126)  pack w4
//   [126,270) pack w5   [270,558) pack w6  [558,2606) conv1
__global__ void __launch_bounds__(256)
prep_kernel(const float* __restrict__ x,  const float* __restrict__ w1,
            const float* __restrict__ b1, const float* __restrict__ s1, const float* __restrict__ t1,
            const float* __restrict__ w2, const float* __restrict__ w3, const float* __restrict__ w4,
            const float* __restrict__ w5, const float* __restrict__ w6) {
    int bid = blockIdx.x, tid = threadIdx.x;
    if      (bid < 18)  pack_dev(w2, g_w2p, 128, 128, bid * 256 + tid);
    else if (bid < 54)  pack_dev(w3, g_w3p, 128, 256, (bid - 18)  * 256 + tid);
    else if (bid < 126) pack_dev(w4, g_w4p, 256, 256, (bid - 54)  * 256 + tid);
    else if (bid < 270) pack_dev(w5, g_w5p, 256, 512, (bid - 126) * 256 + tid);
    else if (bid < 558) pack_dev(w6, g_w6p, 512, 512, (bid - 270) * 256 + tid);
    else                conv1_dev(x, w1, b1, s1, t1, bid - 558, tid);
}

// ---------------- generic binary conv v2 (xnor-popcount, full-row accumulators) -------------
// in: packed [N, HW, HW, IW]; wp: [9, IW, CO]; conv 3x3 SAME, relu,
// optional 2x2 maxpool, then bn (mul then add, separate roundings) and
// either binarize/pack or fp out. Conv sums are exact integers.
// Loop order: w outermost (rolled). Weights -> registers once per thread; each
// staged activation word loaded once and reused across all (rr,kx) tap roles.
template<int IW, int CO, int HW, bool POOL, bool FOUT>
__global__ void __launch_bounds__(CO)
bconv2_kernel(const uint32_t* __restrict__ in, const uint32_t* __restrict__ wp,
              const float* __restrict__ scale, const float* __restrict__ bias,
              uint32_t* __restrict__ outb, float* __restrict__ outf) {
    // grid (HW/2, N), block CO; each block computes conv rows r0, r0+1 (full width)
    int yb = blockIdx.x, n = blockIdx.y, co = threadIdx.x;
    int r0 = 2 * yb;
    __shared__ uint32_t sm[4][HW + 2][IW];

    for (int i = threadIdx.x; i < 4 * (HW + 2) * IW; i += CO) {
        int w  = i % IW;
        int xx = (i / IW) % (HW + 2);
        int rr = i / (IW * (HW + 2));
        int yy = r0 - 1 + rr;
        int xs = xx - 1;
        uint32_t v = 0;
        if (yy >= 0 && yy < HW && xs >= 0 && xs < HW)
            v = in[((n * HW + yy) * HW + xs) * IW + w];
        sm[rr][xx][w] = v;
    }
    __syncthreads();

    int mm[2][HW];
    #pragma unroll
    for (int rr = 0; rr < 2; rr++)
        #pragma unroll
        for (int o = 0; o < HW; o++) mm[rr][o] = 0;
    int pw[9];
    #pragma unroll
    for (int t = 0; t < 9; t++) pw[t] = 0;

    #pragma unroll 1
    for (int w = 0; w < IW; w++) {
        uint32_t wt[9];
        #pragma unroll
        for (int t = 0; t < 9; t++) {
            wt[t] = wp[(t * IW + w) * CO + co];   // coalesced across co
            pw[t] += __popc(wt[t]);
        }
        #pragma unroll
        for (int iy = 0; iy < 4; iy++) {
            #pragma unroll
            for (int xx = 0; xx < HW + 2; xx++) {
                uint32_t a = sm[iy][xx][w];       // warp-uniform broadcast load
                #pragma unroll
                for (int rr = 0; rr < 2; rr++) {
                    int ky = iy - rr;
                    if (ky < 0 || ky > 2) continue;           // compile-time
                    #pragma unroll
                    for (int kx = 0; kx < 3; kx++) {
                        int o = xx - kx;                       // output position
                        if (o < 0 || o >= HW) continue;        // compile-time
                        mm[rr][o] += __popc(a ^ wt[ky * 3 + kx]);
                    }
                }
            }
        }
    }

    // convert mismatch counts -> conv sums with exact SAME-padding handling
    float sc = scale[co], tc = bias[co];
    int lane = co & 31, wrp = co >> 5;

    int sums[2][HW];
    #pragma unroll
    for (int rr = 0; rr < 2; rr++) {
        int r = r0 + rr;
        bool top = (r == 0), bot = (r == HW - 1);
        #pragma unroll
        for (int o = 0; o < HW; o++) {
            bool left = (o == 0), right = (o == HW - 1);       // compile-time
            int corr = 0;
            if (top)  corr += pw[0] + pw[1] + pw[2];
            if (bot)  corr += pw[6] + pw[7] + pw[8];
            if (left) {
                corr += pw[0] + pw[3] + pw[6];
                if (top) corr -= pw[0];
                if (bot) corr -= pw[6];
            }
            if (right) {
                corr += pw[2] + pw[5] + pw[8];
                if (top) corr -= pw[2];
                if (bot) corr -= pw[8];
            }
            int nrow = 3 - (top ? 1 : 0) - (bot ? 1 : 0);
            int ncol = 3 - (left ? 1 : 0) - (right ? 1 : 0);
            sums[rr][o] = nrow * ncol * (32 * IW) - 2 * (mm[rr][o] - corr);
        }
    }

    if (POOL) {
        const int HWo = HW / 2;
        #pragma unroll
        for (int xo = 0; xo < HWo; xo++) {
            int p = max(max(sums[0][2 * xo], sums[0][2 * xo + 1]),
                        max(sums[1][2 * xo], sums[1][2 * xo + 1]));
            p = max(p, 0);                                   // relu then pool == pool then clamp 0
            float v = __fadd_rn(__fmul_rn((float)p, sc), tc); // bn: separate roundings
            if (FOUT) {
                outf[((n * HWo + yb) * HWo + xo) * CO + co] = v;
            } else {
                unsigned m = __ballot_sync(0xffffffffu, v > 0.f);
                if (lane == 0)
                    outb[((n * HWo + yb) * HWo + xo) * (CO / 32) + wrp] = m;
            }
        }
    } else {
        #pragma unroll
        for (int rr = 0; rr < 2; rr++) {
            #pragma unroll
            for (int o = 0; o < HW; o++) {
                int s = max(sums[rr][o], 0);
                float v = __fadd_rn(__fmul_rn((float)s, sc), tc);
                unsigned m = __ballot_sync(0xffffffffu, v > 0.f);
                if (lane == 0)
                    outb[((n * HW + r0 + rr) * HW + o) * (CO / 32) + wrp] = m;
            }
        }
    }
}

// ---------------- dense (bhwc,cd) + bias + softmax ----------------
__global__ void dense_softmax_kernel(const float* __restrict__ dw, const float* __restrict__ db,
                                     float* __restrict__ out) {
    __shared__ float sw[512 * 10];
    __shared__ float sb[10];
    for (int i = threadIdx.x; i < 512 * 10; i += blockDim.x) sw[i] = dw[i];
    if (threadIdx.x < 10) sb[threadIdx.x] = db[threadIdx.x];
    __syncthreads();

    int warp = threadIdx.x >> 5, lane = threadIdx.x & 31;
    int row = blockIdx.x * (blockDim.x >> 5) + warp;     // 0..2047
    if (row >= 2048) return;

    float acc[10];
    #pragma unroll
    for (int d = 0; d < 10; d++) acc[d] = 0.f;
    const float* h = g_h6 + row * 512;
    for (int c = lane; c < 512; c += 32) {
        float hv = h[c];
        #pragma unroll
        for (int d = 0; d < 10; d++) acc[d] += hv * sw[c * 10 + d];
    }
    #pragma unroll
    for (int d = 0; d < 10; d++) {
        float v = acc[d];
        #pragma unroll
        for (int o = 16; o; o >>= 1) v += __shfl_xor_sync(0xffffffffu, v, o);
        acc[d] = v;
    }
    if (lane == 0) {
        float mx = -1e30f;
        #pragma unroll
        for (int d = 0; d < 10; d++) {
            acc[d] += sb[d];
            mx = fmaxf(mx, acc[d]);
        }
        float se = 0.f;
        #pragma unroll
        for (int d = 0; d < 10; d++) {
            acc[d] = expf(acc[d] - mx);
            se += acc[d];
        }
        float inv = 1.f / se;
        #pragma unroll
        for (int d = 0; d < 10; d++) out[row * 10 + d] = acc[d] * inv;
    }
}

// ---------------- launch ----------------
extern "C" void kernel_launch(void* const* d_in, const int* in_sizes, int n_in,
                              void* d_out, int out_size) {
    const float *x = nullptr, *w1 = nullptr, *b1 = nullptr;
    const float *w2 = nullptr, *w3 = nullptr, *w4 = nullptr, *w5 = nullptr, *w6 = nullptr;
    const float *bns[7] = {0}, *bnb[7] = {0};
    const float *dw = nullptr, *db = nullptr;
    int c128 = 0, c256 = 0, c512 = 0;
    for (int i = 0; i < n_in; i++) {
        const float* p = (const float*)d_in[i];
        switch (in_sizes[i]) {
            case 393216:  x  = p; break;
            case 3456:    w1 = p; break;
            case 147456:  w2 = p; break;
            case 294912:  w3 = p; break;
            case 589824:  w4 = p; break;
            case 1179648: w5 = p; break;
            case 2359296: w6 = p; break;
            case 5120:    dw = p; break;
            case 10:      db = p; break;
            case 128:   // order in both schemes: b1, bn1_s, bn1_b, bn2_s, bn2_b
                if      (c128 == 0) b1     = p;
                else if (c128 == 1) bns[1] = p;
                else if (c128 == 2) bnb[1] = p;
                else if (c128 == 3) bns[2] = p;
                else                bnb[2] = p;
                c128++; break;
            case 256:   // bn3_s, bn3_b, bn4_s, bn4_b
                if      (c256 == 0) bns[3] = p;
                else if (c256 == 1) bnb[3] = p;
                else if (c256 == 2) bns[4] = p;
                else                bnb[4] = p;
                c256++; break;
            case 512:   // bn5_s, bn5_b, bn6_s, bn6_b
                if      (c512 == 0) bns[5] = p;
                else if (c512 == 1) bnb[5] = p;
                else if (c512 == 2) bns[6] = p;
                else                bnb[6] = p;
                c512++; break;
            default: break;
        }
    }

    void *p_h1, *p_h2, *p_h3, *p_h4, *p_h5, *p_h6;
    void *p_w2, *p_w3, *p_w4, *p_w5, *p_w6;
    cudaGetSymbolAddress(&p_h1, g_h1p);
    cudaGetSymbolAddress(&p_h2, g_h2p);
    cudaGetSymbolAddress(&p_h3, g_h3p);
    cudaGetSymbolAddress(&p_h4, g_h4p);
    cudaGetSymbolAddress(&p_h5, g_h5p);
    cudaGetSymbolAddress(&p_h6, g_h6);
    cudaGetSymbolAddress(&p_w2, g_w2p);
    cudaGetSymbolAddress(&p_w3, g_w3p);
    cudaGetSymbolAddress(&p_w4, g_w4p);
    cudaGetSymbolAddress(&p_w5, g_w5p);
    cudaGetSymbolAddress(&p_w6, g_w6p);

    // fused prep: 5 weight packs + conv1 in one launch (all independent)
    prep_kernel<<<2606, 256>>>(x, w1, b1, bns[1], bnb[1], w2, w3, w4, w5, w6);

    // binary conv stack
    bconv2_kernel<4, 128, 32, true,  false><<<dim3(16, 128), 128>>>(
        (const uint32_t*)p_h1, (const uint32_t*)p_w2, bns[2], bnb[2], (uint32_t*)p_h2, nullptr);
    bconv2_kernel<4, 256, 16, false, false><<<dim3(8, 128), 256>>>(
        (const uint32_t*)p_h2, (const uint32_t*)p_w3, bns[3], bnb[3], (uint32_t*)p_h3, nullptr);
    bconv2_kernel<8, 256, 16, true,  false><<<dim3(8, 128), 256>>>(
        (const uint32_t*)p_h3, (const uint32_t*)p_w4, bns[4], bnb[4], (uint32_t*)p_h4, nullptr);
    bconv2_kernel<8, 512, 8,  false, false><<<dim3(4, 128), 512>>>(
        (const uint32_t*)p_h4, (const uint32_t*)p_w5, bns[5], bnb[5], (uint32_t*)p_h5, nullptr);
    bconv2_kernel<16, 512, 8, true,  true ><<<dim3(4, 128), 512>>>(
        (const uint32_t*)p_h5, (const uint32_t*)p_w6, bns[6], bnb[6], nullptr, (float*)p_h6);

    // dense + softmax: 2048 rows, 1 warp per row
    dense_softmax_kernel<<<256, 256>>>(dw, db, (float*)d_out);
}

// round 12
// speedup vs baseline: 1.0607x; 1.0607x over previous
#include <cuda_runtime.h>
#include <cstdint>
#include <math.h>

// ---------------- device scratch (no allocation allowed) ----------------
__device__ uint32_t g_h1p[128*32*32*4];     // after conv1+bn1, binarized, packed
__device__ uint32_t g_h2p[128*16*16*4];
__device__ uint32_t g_h3p[128*16*16*8];
__device__ uint32_t g_h4p[128*8*8*8];
__device__ uint32_t g_h5p[128*8*8*16];
__device__ float    g_h6 [128*4*4*512];     // fp output after conv6/pool/bn6
__device__ uint32_t g_w2p[9*4*128];
__device__ uint32_t g_w3p[9*4*256];
__device__ uint32_t g_w4p[9*8*256];
__device__ uint32_t g_w5p[9*8*512];
__device__ uint32_t g_w6p[9*16*512];

// ---------------- weight bit-packing (device helper) ----------------
// w: HWIO [3,3,CI,CO] floats -> wp[(tap*IW + word)*CO + co], bit b = (w[tap, word*32+b, co] > 0)
__device__ __forceinline__ void pack_dev(const float* __restrict__ w, uint32_t* __restrict__ wp,
                                         int CI, int CO, int idx) {
    int IW = CI / 32;
    int total = 9 * IW * CO;
    if (idx >= total) return;
    int co   = idx % CO;
    int word = (idx / CO) % IW;
    int tap  = idx / (CO * IW);
    uint32_t bits = 0;
    #pragma unroll 8
    for (int b = 0; b < 32; b++) {
        float v = w[(tap * CI + word * 32 + b) * CO + co];   // coalesced across co
        bits |= (v > 0.f ? 1u : 0u) << b;
    }
    wp[(tap * IW + word) * CO + co] = bits;
}

// ---------------- conv1 (device helper): fp conv 3x3x3->128 + b1 + relu + bn1 + pack ----------
// Numerics bitwise-match the reference: zero-seeded sequential FMA chain over (ky,kx,ci);
// bias added after; relu; bn as separate __fmul_rn then __fadd_rn.
__device__ __forceinline__ void conv1_dev(const float* __restrict__ x, const float* __restrict__ w1,
                                          const float* __restrict__ b1, const float* __restrict__ s1,
                                          const float* __restrict__ t1, int bid, int tid) {
    // bid in [0, 2048): n = bid>>4 (128), yb = bid&15 (16); block handles rows 2yb, 2yb+1
    __shared__ float sx[4][34][3];
    int n = bid >> 4, yb = bid & 15;
    int half = tid >> 7, c = tid & 127;
    int y = 2 * yb + half;

    for (int i = tid; i < 4 * 34 * 3; i += 256) {
        int ci = i % 3;
        int xx = (i / 3) % 34;
        int r  = i / (3 * 34);
        int yy = 2 * yb - 1 + r;
        int xs = xx - 1;
        float v = 0.f;
        if (yy >= 0 && yy < 32 && xs >= 0 && xs < 32)
            v = x[((n * 32 + yy) * 32 + xs) * 3 + ci];
        sx[r][xx][ci] = v;
    }
    __syncthreads();

    float wr[27];
    #pragma unroll
    for (int k = 0; k < 27; k++) wr[k] = w1[k * 128 + c];
    float bb = b1[c], sc = s1[c], tc = t1[c];
    int lane = c & 31, wrp = c >> 5;

    for (int xo = 0; xo < 32; xo++) {
        float acc = 0.f;
        #pragma unroll
        for (int ky = 0; ky < 3; ky++)
            #pragma unroll
            for (int kx = 0; kx < 3; kx++)
                #pragma unroll
                for (int ci = 0; ci < 3; ci++)
                    acc = fmaf(sx[half + ky][xo + kx][ci], wr[(ky * 3 + kx) * 3 + ci], acc);
        float z = __fadd_rn(acc, bb);
        float r = fmaxf(z, 0.f);
        float v = __fadd_rn(__fmul_rn(r, sc), tc);
        unsigned m = __ballot_sync(0xffffffffu, v > 0.f);
        if (lane == 0) g_h1p[((n * 32 + y) * 32 + xo) * 4 + wrp] = m;
    }
}

// ---------------- fused prep: all 5 weight packs + conv1 (mutually independent) -------------
// block layout (256 threads each):
//   [0,18)    pack w2   [18,54)  pack w3   [54,126)  pack w4
//   [126,270) pack w5   [270,558) pack w6  [558,2606) conv1
__global__ void __launch_bounds__(256)
prep_kernel(const float* __restrict__ x,  const float* __restrict__ w1,
            const float* __restrict__ b1, const float* __restrict__ s1, const float* __restrict__ t1,
            const float* __restrict__ w2, const float* __restrict__ w3, const float* __restrict__ w4,
            const float* __restrict__ w5, const float* __restrict__ w6) {
    int bid = blockIdx.x, tid = threadIdx.x;
    if      (bid < 18)  pack_dev(w2, g_w2p, 128, 128, bid * 256 + tid);
    else if (bid < 54)  pack_dev(w3, g_w3p, 128, 256, (bid - 18)  * 256 + tid);
    else if (bid < 126) pack_dev(w4, g_w4p, 256, 256, (bid - 54)  * 256 + tid);
    else if (bid < 270) pack_dev(w5, g_w5p, 256, 512, (bid - 126) * 256 + tid);
    else if (bid < 558) pack_dev(w6, g_w6p, 512, 512, (bid - 270) * 256 + tid);
    else                conv1_dev(x, w1, b1, s1, t1, bid - 558, tid);
}

// ---------------- binary conv v3: NX-column tiles, 128-thread channel slices ----------------
// in: packed [N, HW, HW, IW]; wp: [9, IW, CO]; conv 3x3 SAME, relu,
// optional 2x2 maxpool, bn (mul then add, separate roundings), binarize/pack or fp out.
// grid = ((HW/2)*(HW/NX), N, CO/128); block = 128 threads (one co each).
// Per-thread accumulators mm[2][NX] (NX=8 -> 16 regs) keep register count low for occupancy.
template<int IW, int CO, int HW, int NX, bool POOL, bool FOUT>
__global__ void __launch_bounds__(128)
bconv3_kernel(const uint32_t* __restrict__ in, const uint32_t* __restrict__ wp,
              const float* __restrict__ scale, const float* __restrict__ bias,
              uint32_t* __restrict__ outb, float* __restrict__ outf) {
    const int XB = HW / NX;
    int bx = blockIdx.x, n = blockIdx.y;
    int co = blockIdx.z * 128 + threadIdx.x;
    int xchunk = bx % XB, yb = bx / XB;
    int r0 = 2 * yb, xb = xchunk * NX;

    __shared__ uint32_t sm[4][NX + 2][IW];
    for (int i = threadIdx.x; i < 4 * (NX + 2) * IW; i += 128) {
        int w  = i % IW;
        int xx = (i / IW) % (NX + 2);
        int rr = i / (IW * (NX + 2));
        int yy = r0 - 1 + rr;
        int xs = xb + xx - 1;
        uint32_t v = 0;
        if (yy >= 0 && yy < HW && xs >= 0 && xs < HW)
            v = in[((n * HW + yy) * HW + xs) * IW + w];
        sm[rr][xx][w] = v;
    }
    __syncthreads();

    int mm[2][NX];
    #pragma unroll
    for (int rr = 0; rr < 2; rr++)
        #pragma unroll
        for (int o = 0; o < NX; o++) mm[rr][o] = 0;
    int pw[9];
    #pragma unroll
    for (int t = 0; t < 9; t++) pw[t] = 0;

    #pragma unroll 1
    for (int w = 0; w < IW; w++) {
        uint32_t wt[9];
        #pragma unroll
        for (int t = 0; t < 9; t++) {
            wt[t] = wp[(t * IW + w) * CO + co];   // coalesced across co
            pw[t] += __popc(wt[t]);
        }
        #pragma unroll
        for (int iy = 0; iy < 4; iy++) {
            #pragma unroll
            for (int xx = 0; xx < NX + 2; xx++) {
                uint32_t a = sm[iy][xx][w];       // warp-uniform broadcast load
                #pragma unroll
                for (int rr = 0; rr < 2; rr++) {
                    int ky = iy - rr;
                    if (ky < 0 || ky > 2) continue;            // compile-time
                    #pragma unroll
                    for (int kx = 0; kx < 3; kx++) {
                        int o = xx - kx;                        // tile-local output col
                        if (o < 0 || o >= NX) continue;         // compile-time
                        mm[rr][o] += __popc(a ^ wt[ky * 3 + kx]);
                    }
                }
            }
        }
    }

    // mismatch counts -> conv sums with exact SAME-padding handling
    float sc = scale[co], tc = bias[co];
    int lane = co & 31, wrp = co >> 5;

    int sums[2][NX];
    #pragma unroll
    for (int rr = 0; rr < 2; rr++) {
        int r = r0 + rr;
        bool top = (r == 0), bot = (r == HW - 1);
        #pragma unroll
        for (int o = 0; o < NX; o++) {
            int gx = xb + o;
            bool left = (gx == 0), right = (gx == HW - 1);
            int corr = 0;
            if (top)  corr += pw[0] + pw[1] + pw[2];
            if (bot)  corr += pw[6] + pw[7] + pw[8];
            if (left) {
                corr += pw[0] + pw[3] + pw[6];
                if (top) corr -= pw[0];
                if (bot) corr -= pw[6];
            }
            if (right) {
                corr += pw[2] + pw[5] + pw[8];
                if (top) corr -= pw[2];
                if (bot) corr -= pw[8];
            }
            int nrow = 3 - (top ? 1 : 0) - (bot ? 1 : 0);
            int ncol = 3 - (left ? 1 : 0) - (right ? 1 : 0);
            sums[rr][o] = nrow * ncol * (32 * IW) - 2 * (mm[rr][o] - corr);
        }
    }

    if (POOL) {
        const int HWo = HW / 2;
        #pragma unroll
        for (int xo2 = 0; xo2 < NX / 2; xo2++) {
            int p = max(max(sums[0][2 * xo2], sums[0][2 * xo2 + 1]),
                        max(sums[1][2 * xo2], sums[1][2 * xo2 + 1]));
            p = max(p, 0);                                     // relu then pool == pool then clamp 0
            float v = __fadd_rn(__fmul_rn((float)p, sc), tc);  // bn: separate roundings
            int xo = xb / 2 + xo2;
            if (FOUT) {
                outf[((n * HWo + yb) * HWo + xo) * CO + co] = v;
            } else {
                unsigned m = __ballot_sync(0xffffffffu, v > 0.f);
                if (lane == 0)
                    outb[((n * HWo + yb) * HWo + xo) * (CO / 32) + wrp] = m;
            }
        }
    } else {
        #pragma unroll
        for (int rr = 0; rr < 2; rr++) {
            #pragma unroll
            for (int o = 0; o < NX; o++) {
                int s = max(sums[rr][o], 0);
                float v = __fadd_rn(__fmul_rn((float)s, sc), tc);
                unsigned m = __ballot_sync(0xffffffffu, v > 0.f);
                if (lane == 0)
                    outb[((n * HW + r0 + rr) * HW + (xb + o)) * (CO / 32) + wrp] = m;
            }
        }
    }
}

// ---------------- dense (bhwc,cd) + bias + softmax ----------------
__global__ void dense_softmax_kernel(const float* __restrict__ dw, const float* __restrict__ db,
                                     float* __restrict__ out) {
    __shared__ float sw[512 * 10];
    __shared__ float sb[10];
    for (int i = threadIdx.x; i < 512 * 10; i += blockDim.x) sw[i] = dw[i];
    if (threadIdx.x < 10) sb[threadIdx.x] = db[threadIdx.x];
    __syncthreads();

    int warp = threadIdx.x >> 5, lane = threadIdx.x & 31;
    int row = blockIdx.x * (blockDim.x >> 5) + warp;     // 0..2047
    if (row >= 2048) return;

    float acc[10];
    #pragma unroll
    for (int d = 0; d < 10; d++) acc[d] = 0.f;
    const float* h = g_h6 + row * 512;
    for (int c = lane; c < 512; c += 32) {
        float hv = h[c];
        #pragma unroll
        for (int d = 0; d < 10; d++) acc[d] += hv * sw[c * 10 + d];
    }
    #pragma unroll
    for (int d = 0; d < 10; d++) {
        float v = acc[d];
        #pragma unroll
        for (int o = 16; o; o >>= 1) v += __shfl_xor_sync(0xffffffffu, v, o);
        acc[d] = v;
    }
    if (lane == 0) {
        float mx = -1e30f;
        #pragma unroll
        for (int d = 0; d < 10; d++) {
            acc[d] += sb[d];
            mx = fmaxf(mx, acc[d]);
        }
        float se = 0.f;
        #pragma unroll
        for (int d = 0; d < 10; d++) {
            acc[d] = expf(acc[d] - mx);
            se += acc[d];
        }
        float inv = 1.f / se;
        #pragma unroll
        for (int d = 0; d < 10; d++) out[row * 10 + d] = acc[d] * inv;
    }
}

// ---------------- launch ----------------
extern "C" void kernel_launch(void* const* d_in, const int* in_sizes, int n_in,
                              void* d_out, int out_size) {
    const float *x = nullptr, *w1 = nullptr, *b1 = nullptr;
    const float *w2 = nullptr, *w3 = nullptr, *w4 = nullptr, *w5 = nullptr, *w6 = nullptr;
    const float *bns[7] = {0}, *bnb[7] = {0};
    const float *dw = nullptr, *db = nullptr;
    int c128 = 0, c256 = 0, c512 = 0;
    for (int i = 0; i < n_in; i++) {
        const float* p = (const float*)d_in[i];
        switch (in_sizes[i]) {
            case 393216:  x  = p; break;
            case 3456:    w1 = p; break;
            case 147456:  w2 = p; break;
            case 294912:  w3 = p; break;
            case 589824:  w4 = p; break;
            case 1179648: w5 = p; break;
            case 2359296: w6 = p; break;
            case 5120:    dw = p; break;
            case 10:      db = p; break;
            case 128:   // order in both schemes: b1, bn1_s, bn1_b, bn2_s, bn2_b
                if      (c128 == 0) b1     = p;
                else if (c128 == 1) bns[1] = p;
                else if (c128 == 2) bnb[1] = p;
                else if (c128 == 3) bns[2] = p;
                else                bnb[2] = p;
                c128++; break;
            case 256:   // bn3_s, bn3_b, bn4_s, bn4_b
                if      (c256 == 0) bns[3] = p;
                else if (c256 == 1) bnb[3] = p;
                else if (c256 == 2) bns[4] = p;
                else                bnb[4] = p;
                c256++; break;
            case 512:   // bn5_s, bn5_b, bn6_s, bn6_b
                if      (c512 == 0) bns[5] = p;
                else if (c512 == 1) bnb[5] = p;
                else if (c512 == 2) bns[6] = p;
                else                bnb[6] = p;
                c512++; break;
            default: break;
        }
    }

    void *p_h1, *p_h2, *p_h3, *p_h4, *p_h5, *p_h6;
    void *p_w2, *p_w3, *p_w4, *p_w5, *p_w6;
    cudaGetSymbolAddress(&p_h1, g_h1p);
    cudaGetSymbolAddress(&p_h2, g_h2p);
    cudaGetSymbolAddress(&p_h3, g_h3p);
    cudaGetSymbolAddress(&p_h4, g_h4p);
    cudaGetSymbolAddress(&p_h5, g_h5p);
    cudaGetSymbolAddress(&p_h6, g_h6);
    cudaGetSymbolAddress(&p_w2, g_w2p);
    cudaGetSymbolAddress(&p_w3, g_w3p);
    cudaGetSymbolAddress(&p_w4, g_w4p);
    cudaGetSymbolAddress(&p_w5, g_w5p);
    cudaGetSymbolAddress(&p_w6, g_w6p);

    // fused prep: 5 weight packs + conv1 in one launch (all independent)
    prep_kernel<<<2606, 256>>>(x, w1, b1, bns[1], bnb[1], w2, w3, w4, w5, w6);

    // binary conv stack: grid ((HW/2)*(HW/NX), N, CO/128), block 128
    bconv3_kernel<4, 128, 32, 8, true,  false><<<dim3(16 * 4, 128, 1), 128>>>(
        (const uint32_t*)p_h1, (const uint32_t*)p_w2, bns[2], bnb[2], (uint32_t*)p_h2, nullptr);
    bconv3_kernel<4, 256, 16, 8, false, false><<<dim3(8 * 2, 128, 2), 128>>>(
        (const uint32_t*)p_h2, (const uint32_t*)p_w3, bns[3], bnb[3], (uint32_t*)p_h3, nullptr);
    bconv3_kernel<8, 256, 16, 8, true,  false><<<dim3(8 * 2, 128, 2), 128>>>(
        (const uint32_t*)p_h3, (const uint32_t*)p_w4, bns[4], bnb[4], (uint32_t*)p_h4, nullptr);
    bconv3_kernel<8, 512, 8, 8,  false, false><<<dim3(4 * 1, 128, 4), 128>>>(
        (const uint32_t*)p_h4, (const uint32_t*)p_w5, bns[5], bnb[5], (uint32_t*)p_h5, nullptr);
    bconv3_kernel<16, 512, 8, 8, true,  true ><<<dim3(4 * 1, 128, 4), 128>>>(
        (const uint32_t*)p_h5, (const uint32_t*)p_w6, bns[6], bnb[6], nullptr, (float*)p_h6);

    // dense + softmax: 2048 rows, 1 warp per row
    dense_softmax_kernel<<<256, 256>>>(dw, db, (float*)d_out);
}